// round 6
// baseline (speedup 1.0000x reference)
#include <cuda_runtime.h>

// Problem constants (fixed by the reference)
constexpr int B  = 8;
constexpr int C  = 256;
constexpr int H  = 64;
constexpr int W  = 64;
constexpr int WC = 16;          // weight channels
constexpr int G  = C / WC;      // 16 groups sharing each weight
constexpr int HW = H * W;       // 4096
constexpr int Q  = HW / 4;      // float4 pixel-quads per plane = 1024

// One thread = one (b, wc, 4-pixel quad) over all 16 groups.
// Tap-row-outer ordering keeps only 3 weight vectors + 4 group rows + 4
// accumulators live (~70 regs), allowing 3 CTAs/SM while preserving 7
// independent LDG.128 per phase. Weights are re-read per group-block
// (same addresses -> L1 hits).
__global__ __launch_bounds__(256, 3) void agg_kernel_v4(
    const float* __restrict__ x,
    const float* __restrict__ w,
    float* __restrict__ out)
{
    const int idx = blockIdx.x * blockDim.x + threadIdx.x;  // 0 .. B*WC*Q-1
    const int q   = idx & (Q - 1);          // quad index within plane
    const int wc  = (idx >> 10) & (WC - 1);
    const int b   = idx >> 14;
    const int p4  = q << 2;                 // first pixel of the quad
    const int oh  = q >> 4;                 // 16 quads per row

    const bool rowL = ((q & 15) == 0);      // quad starts at ow=0
    const bool rowR = ((q & 15) == 15);     // quad ends at ow=63
    const bool ym   = (oh > 0);
    const bool yp   = (oh < H - 1);

    const float4* wp = (const float4*)(w + ((size_t)(b * WC + wc) * 9) * HW + p4);
    const float* xbase = x   + (size_t)(b * C + wc) * HW + p4;
    float*       obase = out + (size_t)(b * C + wc) * HW + p4;

    const float4 z4 = make_float4(0.f, 0.f, 0.f, 0.f);

    #pragma unroll
    for (int blk = 0; blk < 4; blk++) {
        float4 acc[4];
        #pragma unroll
        for (int gg = 0; gg < 4; gg++) acc[gg] = z4;

        #pragma unroll
        for (int r = 0; r < 3; r++) {
            // 3 weight vectors for this tap row (L1-hit reloads after blk 0).
            const float4 wl = wp[(size_t)(3 * r + 0) * Q];
            const float4 wm = wp[(size_t)(3 * r + 1) * Q];
            const float4 wr = wp[(size_t)(3 * r + 2) * Q];

            const bool valid = (r == 0) ? ym : (r == 2) ? yp : true;

            // Batch the 4 group-row loads (independent LDG.128).
            float4 c[4];
            #pragma unroll
            for (int gg = 0; gg < 4; gg++) {
                const float* xc = xbase + (size_t)(blk * 4 + gg) * WC * HW;
                c[gg] = valid ? *(const float4*)(xc + (r - 1) * W) : z4;
            }

            #pragma unroll
            for (int gg = 0; gg < 4; gg++) {
                const float4 cc = c[gg];
                float lf = __shfl_up_sync(0xffffffffu, cc.w, 1);
                float rt = __shfl_down_sync(0xffffffffu, cc.x, 1);
                if (rowL) lf = 0.f;
                if (rowR) rt = 0.f;

                acc[gg].x += lf   * wl.x + cc.x * wm.x + cc.y * wr.x;
                acc[gg].y += cc.x * wl.y + cc.y * wm.y + cc.z * wr.y;
                acc[gg].z += cc.y * wl.z + cc.z * wm.z + cc.w * wr.z;
                acc[gg].w += cc.z * wl.w + cc.w * wm.w + rt   * wr.w;
            }
        }

        #pragma unroll
        for (int gg = 0; gg < 4; gg++)
            *(float4*)(obase + (size_t)(blk * 4 + gg) * WC * HW) = acc[gg];
    }
}

extern "C" void kernel_launch(void* const* d_in, const int* in_sizes, int n_in,
                              void* d_out, int out_size)
{
    const float* x = (const float*)d_in[0];   // (8,256,64,64) f32
    const float* w = (const float*)d_in[1];   // (8,16,9,4096) f32
    float* out = (float*)d_out;               // (8,256,64,64) f32

    const int total = B * WC * Q;             // 131072 threads
    agg_kernel_v4<<<total / 256, 256>>>(x, w, out);
}

// round 7
// speedup vs baseline: 1.1671x; 1.1671x over previous
#include <cuda_runtime.h>

// Problem constants (fixed by the reference)
constexpr int B  = 8;
constexpr int C  = 256;
constexpr int H  = 64;
constexpr int W  = 64;
constexpr int WC = 16;          // weight channels
constexpr int G  = C / WC;      // 16 groups sharing each weight
constexpr int HW = H * W;       // 4096
constexpr int Q  = HW / 4;      // float4 quads per plane = 1024

// One thread = one (b, wc, 2-row pair of quads) over all 16 groups.
//  - 4 x-rows per group feed BOTH output rows (vertical reuse).
//  - shuffles per loaded row are shared by both output rows.
//  - 18 weight float4s stay register-resident across all groups.
//  - 64-thread CTAs, 8/SM (reg cap 128): grid=1024 fits in ONE wave
//    (capacity 1184), near-perfect SM balance.
__global__ __launch_bounds__(64, 8) void agg_kernel_v5(
    const float* __restrict__ x,
    const float* __restrict__ w,
    float* __restrict__ out)
{
    const int idx  = blockIdx.x * 64 + threadIdx.x;  // 0 .. 65535
    const int q2   = idx & 511;            // 32 row-pairs x 16 quad-cols
    const int wc   = (idx >> 9) & (WC - 1);
    const int b    = idx >> 13;
    const int qcol = q2 & 15;
    const int oh   = (q2 >> 4) << 1;       // even output row
    const int p4   = oh * W + qcol * 4;    // first pixel of top quad

    const bool rowL = (qcol == 0);
    const bool rowR = (qcol == 15);
    const bool ym   = (oh > 0);            // x row oh-1 exists
    const bool yp   = (oh < H - 2);        // x row oh+2 exists

    // Weights: 9 taps for output row oh (wv0) and row oh+1 (wv1).
    const float4* wp = (const float4*)(w + ((size_t)(b * WC + wc) * 9) * HW + p4);
    float4 wv0[9], wv1[9];
    #pragma unroll
    for (int t = 0; t < 9; t++) {
        wv0[t] = wp[(size_t)t * Q];
        wv1[t] = wp[(size_t)t * Q + 16];   // +64 floats = next row
    }

    const float* xbase = x   + (size_t)(b * C + wc) * HW + p4;
    float*       obase = out + (size_t)(b * C + wc) * HW + p4;

    const float4 z4 = make_float4(0.f, 0.f, 0.f, 0.f);

    // Load the 4 x-rows (oh-1 .. oh+2) for one group into c[0..3].
    auto load_rows = [&](float4* c, int g) {
        const float* xc = xbase + (size_t)g * WC * HW;
        c[0] = ym ? *(const float4*)(xc - W)     : z4;
        c[1] =      *(const float4*)(xc);
        c[2] =      *(const float4*)(xc + W);
        c[3] = yp ? *(const float4*)(xc + 2 * W) : z4;
    };

    float4 c[4];
    load_rows(c, 0);

    #pragma unroll
    for (int g = 0; g < G; g++) {
        // Prefetch next group's rows before computing this one.
        float4 n[4];
        if (g < G - 1) load_rows(n, g + 1);

        float4 acc0 = z4, acc1 = z4;

        #pragma unroll
        for (int a = 0; a < 4; a++) {
            const float4 cc = c[a];
            float lf = __shfl_up_sync(0xffffffffu, cc.w, 1);
            float rt = __shfl_down_sync(0xffffffffu, cc.x, 1);
            if (rowL) lf = 0.f;
            if (rowR) rt = 0.f;

            if (a < 3) {   // row contributes to output oh with tap row a
                const float4 wl = wv0[3 * a + 0];
                const float4 wm = wv0[3 * a + 1];
                const float4 wr = wv0[3 * a + 2];
                acc0.x += lf   * wl.x + cc.x * wm.x + cc.y * wr.x;
                acc0.y += cc.x * wl.y + cc.y * wm.y + cc.z * wr.y;
                acc0.z += cc.y * wl.z + cc.z * wm.z + cc.w * wr.z;
                acc0.w += cc.z * wl.w + cc.w * wm.w + rt   * wr.w;
            }
            if (a > 0) {   // row contributes to output oh+1 with tap row a-1
                const float4 wl = wv1[3 * (a - 1) + 0];
                const float4 wm = wv1[3 * (a - 1) + 1];
                const float4 wr = wv1[3 * (a - 1) + 2];
                acc1.x += lf   * wl.x + cc.x * wm.x + cc.y * wr.x;
                acc1.y += cc.x * wl.y + cc.y * wm.y + cc.z * wr.y;
                acc1.z += cc.y * wl.z + cc.z * wm.z + cc.w * wr.z;
                acc1.w += cc.z * wl.w + cc.w * wm.w + rt   * wr.w;
            }
        }

        float* op = obase + (size_t)g * WC * HW;
        *(float4*)(op)     = acc0;
        *(float4*)(op + W) = acc1;

        if (g < G - 1) {
            #pragma unroll
            for (int a = 0; a < 4; a++) c[a] = n[a];
        }
    }
}

extern "C" void kernel_launch(void* const* d_in, const int* in_sizes, int n_in,
                              void* d_out, int out_size)
{
    const float* x = (const float*)d_in[0];   // (8,256,64,64) f32
    const float* w = (const float*)d_in[1];   // (8,16,9,4096) f32
    float* out = (float*)d_out;               // (8,256,64,64) f32

    const int total = B * WC * (Q / 2);       // 65536 threads (2 rows each)
    agg_kernel_v5<<<total / 64, 64>>>(x, w, out);
}

// round 9
// speedup vs baseline: 1.2274x; 1.0517x over previous
#include <cuda_runtime.h>

// Problem constants (fixed by the reference)
constexpr int B  = 8;
constexpr int C  = 256;
constexpr int H  = 64;
constexpr int W  = 64;
constexpr int WC = 16;          // weight channels
constexpr int G  = C / WC;      // 16 groups sharing each weight
constexpr int HW = H * W;       // 4096
constexpr int Q  = HW / 4;      // float4 quads per plane = 1024

// One thread = one (b, wc, 2-row pair of quads) over all 16 groups.
//  - 4 x-rows per group feed BOTH output rows (vertical reuse: 2 loads/row
//    instead of 3, shuffles shared by both outputs).
//  - 18 weight float4s stay register-resident across all 16 groups.
//  - next group's 4 rows are prefetched before computing the current one
//    (8 LDG.128 in flight during compute).
//  - 64-thread CTAs, min 7/SM (reg cap ~144, no spill): grid=1024 fits in
//    ONE wave (capacity 1036), near-perfect SM balance.
__global__ __launch_bounds__(64, 7) void agg_kernel_v6(
    const float* __restrict__ x,
    const float* __restrict__ w,
    float* __restrict__ out)
{
    const int idx  = blockIdx.x * 64 + threadIdx.x;  // 0 .. 65535
    const int q2   = idx & 511;            // 32 row-pairs x 16 quad-cols
    const int wc   = (idx >> 9) & (WC - 1);
    const int b    = idx >> 13;
    const int qcol = q2 & 15;
    const int oh   = (q2 >> 4) << 1;       // even output row
    const int p4   = oh * W + qcol * 4;    // first pixel of top quad

    const bool rowL = (qcol == 0);
    const bool rowR = (qcol == 15);
    const bool ym   = (oh > 0);            // x row oh-1 exists
    const bool yp   = (oh < H - 2);        // x row oh+2 exists

    // Weights: 9 taps for output row oh (wv0) and row oh+1 (wv1).
    const float4* wp = (const float4*)(w + ((size_t)(b * WC + wc) * 9) * HW + p4);
    float4 wv0[9], wv1[9];
    #pragma unroll
    for (int t = 0; t < 9; t++) {
        wv0[t] = wp[(size_t)t * Q];
        wv1[t] = wp[(size_t)t * Q + 16];   // +64 floats = next row
    }

    const float* xbase = x   + (size_t)(b * C + wc) * HW + p4;
    float*       obase = out + (size_t)(b * C + wc) * HW + p4;

    const float4 z4 = make_float4(0.f, 0.f, 0.f, 0.f);

    // Load the 4 x-rows (oh-1 .. oh+2) for group g into c[0..3].
    auto load_rows = [&](float4* c, int g) {
        const float* xc = xbase + (size_t)g * WC * HW;
        c[0] = ym ? *(const float4*)(xc - W)     : z4;
        c[1] =      *(const float4*)(xc);
        c[2] =      *(const float4*)(xc + W);
        c[3] = yp ? *(const float4*)(xc + 2 * W) : z4;
    };

    float4 buf0[4], buf1[4];
    load_rows(buf0, 0);

    #pragma unroll
    for (int g = 0; g < G; g++) {
        float4* c = (g & 1) ? buf1 : buf0;
        float4* n = (g & 1) ? buf0 : buf1;

        // Prefetch next group's rows before computing this one.
        if (g < G - 1) load_rows(n, g + 1);

        float4 acc0 = z4, acc1 = z4;

        #pragma unroll
        for (int a = 0; a < 4; a++) {
            const float4 cc = c[a];
            float lf = __shfl_up_sync(0xffffffffu, cc.w, 1);
            float rt = __shfl_down_sync(0xffffffffu, cc.x, 1);
            if (rowL) lf = 0.f;
            if (rowR) rt = 0.f;

            if (a < 3) {   // contributes to output row oh via tap row a
                const float4 wl = wv0[3 * a + 0];
                const float4 wm = wv0[3 * a + 1];
                const float4 wr = wv0[3 * a + 2];
                acc0.x += lf   * wl.x + cc.x * wm.x + cc.y * wr.x;
                acc0.y += cc.x * wl.y + cc.y * wm.y + cc.z * wr.y;
                acc0.z += cc.y * wl.z + cc.z * wm.z + cc.w * wr.z;
                acc0.w += cc.z * wl.w + cc.w * wm.w + rt   * wr.w;
            }
            if (a > 0) {   // contributes to output row oh+1 via tap row a-1
                const float4 wl = wv1[3 * (a - 1) + 0];
                const float4 wm = wv1[3 * (a - 1) + 1];
                const float4 wr = wv1[3 * (a - 1) + 2];
                acc1.x += lf   * wl.x + cc.x * wm.x + cc.y * wr.x;
                acc1.y += cc.x * wl.y + cc.y * wm.y + cc.z * wr.y;
                acc1.z += cc.y * wl.z + cc.z * wm.z + cc.w * wr.z;
                acc1.w += cc.z * wl.w + cc.w * wm.w + rt   * wr.w;
            }
        }

        float* op = obase + (size_t)g * WC * HW;
        *(float4*)(op)     = acc0;
        *(float4*)(op + W) = acc1;
    }
}

extern "C" void kernel_launch(void* const* d_in, const int* in_sizes, int n_in,
                              void* d_out, int out_size)
{
    const float* x = (const float*)d_in[0];   // (8,256,64,64) f32
    const float* w = (const float*)d_in[1];   // (8,16,9,4096) f32
    float* out = (float*)d_out;               // (8,256,64,64) f32

    const int total = B * WC * (Q / 2);       // 65536 threads (2 rows each)
    agg_kernel_v6<<<total / 64, 64>>>(x, w, out);
}